// round 1
// baseline (speedup 1.0000x reference)
#include <cuda_runtime.h>
#include <cuda_bf16.h>
#include <math.h>

// ---------------- problem constants ----------------
#define BATCH   64
#define SEQ     512
#define EDIM    512
#define HDIM    1024
#define M0      (BATCH*SEQ)      // 32768 level-0 nodes

// ---------------- device scratch (allocation-free rule) ----------------
__device__ float g_HB0[(size_t)M0 * HDIM];            // 128 MB  level outputs (even levels)
__device__ float g_HB1[(size_t)(M0/2) * HDIM];        // 64 MB   level outputs (odd levels)
__device__ float g_PRE[(size_t)M0 * 2 * HDIM];        // 256 MB  pre-activations
__device__ float g_RH [(size_t)(M0/2) * 2 * HDIM];    // 128 MB  [r*hl | r*hr]
__device__ float g_Z  [(size_t)(M0/2) * HDIM];        // 64 MB   z gate
__device__ float g_W0 [(size_t)EDIM * 2 * HDIM];      // [W_z | W_h]            (512 x 2048)
__device__ float g_UZR[(size_t)2*HDIM * 2*HDIM];      // [[Uzl,Url],[Uzr,Urr]]  (2048 x 2048)
__device__ float g_UH [(size_t)2*HDIM * HDIM];        // [Uhl ; Uhr]            (2048 x 1024)
__device__ float g_BL0[2*HDIM];                       // [bz_sum | bh_sum]
__device__ float g_BZR[2*HDIM];                       // [bz_sum | br_sum]
__device__ float g_BH [HDIM];                         // bh_sum

// ---------------- weight packing ----------------
__global__ void pack_kernel(
    const float* __restrict__ Uzl, const float* __restrict__ Url,
    const float* __restrict__ Uzr, const float* __restrict__ Urr,
    const float* __restrict__ Uhl, const float* __restrict__ Uhr,
    const float* __restrict__ Wz,  const float* __restrict__ Wh,
    const float* __restrict__ bz,  const float* __restrict__ bzl, const float* __restrict__ bzr,
    const float* __restrict__ br,  const float* __restrict__ brl, const float* __restrict__ brr,
    const float* __restrict__ bh,  const float* __restrict__ bhl, const float* __restrict__ bhr)
{
    int idx = blockIdx.x * blockDim.x + threadIdx.x;   // covers 2048*2048
    if (idx < 2048*2048) {
        int k = idx >> 11, j = idx & 2047;
        float v;
        if (k < 1024) v = (j < 1024) ? Uzl[k*1024 + j]        : Url[k*1024 + (j-1024)];
        else          v = (j < 1024) ? Uzr[(k-1024)*1024 + j] : Urr[(k-1024)*1024 + (j-1024)];
        g_UZR[idx] = v;
    }
    if (idx < 2048*1024) {
        g_UH[idx] = (idx < 1024*1024) ? Uhl[idx] : Uhr[idx - 1024*1024];
    }
    if (idx < 512*2048) {
        int k = idx >> 11, j = idx & 2047;
        g_W0[idx] = (j < 1024) ? Wz[k*1024 + j] : Wh[k*1024 + (j-1024)];
    }
    if (idx < 1024) {
        float bzs = bz[idx] + bzl[idx] + bzr[idx];
        float brs = br[idx] + brl[idx] + brr[idx];
        float bhs = bh[idx] + bhl[idx] + bhr[idx];
        g_BZR[idx] = bzs; g_BZR[1024 + idx] = brs;
        g_BH[idx]  = bhs;
        g_BL0[idx] = bzs; g_BL0[1024 + idx] = bhs;
    }
}

// ---------------- fp32 SIMT GEMM: C = A(MxK) @ B(KxN) + bias ----------------
// BM=128, BN=128, BK=16, 256 threads, 8x8 per thread, double-buffered smem.
// GATHER: A row r comes from emb[tok[r]*K].
#define TBM 128
#define TBN 128
#define TBK 16

template<bool GATHER>
__global__ void __launch_bounds__(256)
gemm_kernel(const float* __restrict__ A, const int* __restrict__ tok,
            const float* __restrict__ B, const float* __restrict__ bias,
            float* __restrict__ C, int M, int N, int K)
{
    __shared__ float As[2][TBK][TBM + 4];
    __shared__ float Bs[2][TBK][TBN];

    const int tid = threadIdx.x;
    const int bm  = blockIdx.y * TBM;
    const int bn  = blockIdx.x * TBN;
    const int tx  = tid & 15;       // 0..15 -> 8 cols each
    const int ty  = tid >> 4;       // 0..15 -> 8 rows each

    float acc[8][8];
    #pragma unroll
    for (int i = 0; i < 8; i++)
        #pragma unroll
        for (int j = 0; j < 8; j++) acc[i][j] = 0.f;

    const int nt = K / TBK;
    float4 ra[2], rb[2];

    auto loadRegs = [&](int kt) {
        #pragma unroll
        for (int q = 0; q < 2; q++) {
            int s    = tid * 2 + q;          // 0..511
            int arow = s >> 2, ac4 = s & 3;  // A tile: 128 rows x 4 float4
            int gr   = bm + arow;
            if (gr < M) {
                const float* base = GATHER ? (A + (size_t)tok[gr] * K)
                                           : (A + (size_t)gr * K);
                ra[q] = *(const float4*)(base + kt * TBK + ac4 * 4);
            } else {
                ra[q] = make_float4(0.f, 0.f, 0.f, 0.f);
            }
            int brow = s >> 5, bc4 = s & 31; // B tile: 16 rows x 32 float4
            rb[q] = *(const float4*)(B + (size_t)(kt * TBK + brow) * N + bn + bc4 * 4);
        }
    };
    auto storeShared = [&](int buf) {
        #pragma unroll
        for (int q = 0; q < 2; q++) {
            int s    = tid * 2 + q;
            int arow = s >> 2, ac = (s & 3) * 4;
            As[buf][ac + 0][arow] = ra[q].x;
            As[buf][ac + 1][arow] = ra[q].y;
            As[buf][ac + 2][arow] = ra[q].z;
            As[buf][ac + 3][arow] = ra[q].w;
            int brow = s >> 5, bc = (s & 31) * 4;
            *(float4*)&Bs[buf][brow][bc] = rb[q];
        }
    };

    loadRegs(0);
    storeShared(0);
    __syncthreads();

    int buf = 0;
    for (int kt = 0; kt < nt; kt++) {
        if (kt + 1 < nt) loadRegs(kt + 1);
        #pragma unroll
        for (int k = 0; k < TBK; k++) {
            float af[8], bf[8];
            #pragma unroll
            for (int i = 0; i < 8; i++) af[i] = As[buf][k][ty * 8 + i];
            #pragma unroll
            for (int j = 0; j < 8; j++) bf[j] = Bs[buf][k][tx * 8 + j];
            #pragma unroll
            for (int i = 0; i < 8; i++)
                #pragma unroll
                for (int j = 0; j < 8; j++)
                    acc[i][j] = fmaf(af[i], bf[j], acc[i][j]);
        }
        if (kt + 1 < nt) { storeShared(buf ^ 1); buf ^= 1; __syncthreads(); }
    }

    #pragma unroll
    for (int i = 0; i < 8; i++) {
        int gr = bm + ty * 8 + i;
        if (gr < M) {
            #pragma unroll
            for (int j = 0; j < 8; j += 4) {
                int gc = bn + tx * 8 + j;
                float4 v;
                v.x = acc[i][j + 0] + bias[gc + 0];
                v.y = acc[i][j + 1] + bias[gc + 1];
                v.z = acc[i][j + 2] + bias[gc + 2];
                v.w = acc[i][j + 3] + bias[gc + 3];
                *(float4*)(C + (size_t)gr * N + gc) = v;
            }
        }
    }
}

// ---------------- elementwise epilogues ----------------
__device__ __forceinline__ float sigmf(float x) { return 1.f / (1.f + expf(-x)); }

// level 0: pre = [zpre | hpre] (M x 2048) -> h0 = (1-z)*tanh(hpre)
__global__ void e0_kernel(const float* __restrict__ pre, float* __restrict__ h0, int total)
{
    int idx = blockIdx.x * blockDim.x + threadIdx.x;
    if (idx >= total) return;
    int m = idx >> 10, j = idx & 1023;
    size_t o = (size_t)m * 2048 + j;
    float z  = sigmf(pre[o]);
    float ht = tanhf(pre[o + 1024]);
    h0[idx] = (1.f - z) * ht;
}

// after GEMM1: pre = [zpre | rpre]; hprev viewed (M,2048) = [hl|hr] per pair
__global__ void e1_kernel(const float* __restrict__ pre, const float* __restrict__ hprev,
                          float* __restrict__ zb, float* __restrict__ rh, int total)
{
    int idx = blockIdx.x * blockDim.x + threadIdx.x;
    if (idx >= total) return;
    int m = idx >> 10, j = idx & 1023;
    size_t o = (size_t)m * 2048 + j;
    float z = sigmf(pre[o]);
    float r = sigmf(pre[o + 1024]);
    zb[idx] = z;
    rh[o]        = r * hprev[o];
    rh[o + 1024] = r * hprev[o + 1024];
}

// after GEMM2: h = z*(hl+hr) + (1-z)*tanh(pre2)
__global__ void e2_kernel(const float* __restrict__ pre2, const float* __restrict__ zb,
                          const float* __restrict__ hprev, float* __restrict__ hout, int total)
{
    int idx = blockIdx.x * blockDim.x + threadIdx.x;
    if (idx >= total) return;
    int m = idx >> 10, j = idx & 1023;
    size_t o = (size_t)m * 2048 + j;
    float z  = zb[idx];
    float hl = hprev[o];
    float hr = hprev[o + 1024];
    hout[idx] = z * (hl + hr) + (1.f - z) * tanhf(pre2[idx]);
}

// ---------------- launch ----------------
extern "C" void kernel_launch(void* const* d_in, const int* in_sizes, int n_in,
                              void* d_out, int out_size)
{
    const int*   tokens = (const int*)  d_in[0];
    const float* emb    = (const float*)d_in[1];
    const float* W_z  = (const float*)d_in[2];
    const float* b_z  = (const float*)d_in[3];
    const float* U_zl = (const float*)d_in[4];
    const float* b_zl = (const float*)d_in[5];
    const float* U_zr = (const float*)d_in[6];
    const float* b_zr = (const float*)d_in[7];
    const float* W_r  = (const float*)d_in[8];
    const float* b_r  = (const float*)d_in[9];
    const float* U_rl = (const float*)d_in[10];
    const float* b_rl = (const float*)d_in[11];
    const float* U_rr = (const float*)d_in[12];
    const float* b_rr = (const float*)d_in[13];
    const float* W_h  = (const float*)d_in[14];
    const float* b_h  = (const float*)d_in[15];
    const float* U_hl = (const float*)d_in[16];
    const float* b_hl = (const float*)d_in[17];
    const float* U_hr = (const float*)d_in[18];
    const float* b_hr = (const float*)d_in[19];
    (void)W_r; // level-0 r is multiplied by hl=hr=0: unused

    float *HB0, *HB1, *PRE, *RH, *ZB, *W0, *UZR, *UH, *BL0, *BZR, *BH;
    cudaGetSymbolAddress((void**)&HB0, g_HB0);
    cudaGetSymbolAddress((void**)&HB1, g_HB1);
    cudaGetSymbolAddress((void**)&PRE, g_PRE);
    cudaGetSymbolAddress((void**)&RH,  g_RH);
    cudaGetSymbolAddress((void**)&ZB,  g_Z);
    cudaGetSymbolAddress((void**)&W0,  g_W0);
    cudaGetSymbolAddress((void**)&UZR, g_UZR);
    cudaGetSymbolAddress((void**)&UH,  g_UH);
    cudaGetSymbolAddress((void**)&BL0, g_BL0);
    cudaGetSymbolAddress((void**)&BZR, g_BZR);
    cudaGetSymbolAddress((void**)&BH,  g_BH);

    // 1. pack weights/biases
    {
        int total = 2048 * 2048;
        pack_kernel<<<(total + 255) / 256, 256>>>(
            U_zl, U_rl, U_zr, U_rr, U_hl, U_hr, W_z, W_h,
            b_z, b_zl, b_zr, b_r, b_rl, b_rr, b_h, b_hl, b_hr);
    }

    // 2. level 0: word = emb[tokens]; pre = word @ [W_z|W_h] + [bz|bh]
    {
        dim3 grid(2 * HDIM / TBN, M0 / TBM);
        gemm_kernel<true><<<grid, 256>>>(emb, tokens, W0, BL0, PRE, M0, 2 * HDIM, EDIM);
        int total = M0 * HDIM;
        e0_kernel<<<(total + 255) / 256, 256>>>(PRE, HB0, total);
    }

    // 3. tree levels: n = 512 -> 1
    float* hprev = HB0;
    int n = SEQ, lvl = 0;
    while (n > 1) {
        int Mn = BATCH * (n / 2);
        float* hout = (n / 2 == 1) ? (float*)d_out : ((lvl & 1) ? HB0 : HB1);

        // GEMM1: [hl|hr](Mn x 2048) @ UZR(2048 x 2048) + [bz|br]
        {
            dim3 grid(2 * HDIM / TBN, (Mn + TBM - 1) / TBM);
            gemm_kernel<false><<<grid, 256>>>(hprev, nullptr, UZR, BZR, PRE, Mn, 2 * HDIM, 2 * HDIM);
        }
        {
            int total = Mn * HDIM;
            e1_kernel<<<(total + 255) / 256, 256>>>(PRE, hprev, ZB, RH, total);
        }
        // GEMM2: [r*hl|r*hr](Mn x 2048) @ UH(2048 x 1024) + bh
        {
            dim3 grid(HDIM / TBN, (Mn + TBM - 1) / TBM);
            gemm_kernel<false><<<grid, 256>>>(RH, nullptr, UH, BH, PRE, Mn, HDIM, 2 * HDIM);
        }
        {
            int total = Mn * HDIM;
            e2_kernel<<<(total + 255) / 256, 256>>>(PRE, ZB, hprev, hout, total);
        }

        hprev = hout;
        n /= 2;
        lvl++;
    }
    (void)in_sizes; (void)n_in; (void)out_size;
}

// round 3
// speedup vs baseline: 3.1271x; 3.1271x over previous
#include <cuda_runtime.h>
#include <cuda_fp16.h>
#include <math.h>
#include <stdint.h>

// ---------------- problem constants ----------------
#define BATCH   64
#define SEQ     512
#define EDIM    512
#define HDIM    1024
#define M0      (BATCH*SEQ)      // 32768 level-0 nodes

// ---------------- device scratch (allocation-free rule) ----------------
__device__ float g_HB0[(size_t)M0 * HDIM];            // level outputs (even levels)
__device__ float g_HB1[(size_t)(M0/2) * HDIM];        // level outputs (odd levels)
__device__ float g_PRE[(size_t)M0 * 2 * HDIM];        // pre-activations
__device__ float g_RH [(size_t)(M0/2) * 2 * HDIM];    // [r*hl | r*hr]
__device__ float g_Z  [(size_t)(M0/2) * HDIM];        // z gate
// transposed (K-major, [N][K]) packed weights
__device__ float g_W0t [(size_t)(2*HDIM) * EDIM];     // [2048][512]   from [W_z | W_h]
__device__ float g_UZRt[(size_t)(2*HDIM) * (2*HDIM)]; // [2048][2048]  from [[Uzl,Url],[Uzr,Urr]]
__device__ float g_UHt [(size_t)HDIM * (2*HDIM)];     // [1024][2048]  from [Uhl ; Uhr]
__device__ float g_BL0[2*HDIM];                       // [bz_sum | bh_sum]
__device__ float g_BZR[2*HDIM];                       // [bz_sum | br_sum]
__device__ float g_BH [HDIM];                         // bh_sum

// ================= packing kernels =================
// generic 32x32 tiled transpose: dst[c*dpitch + r] = src[r*C + c]
__global__ void transpose_kernel(const float* __restrict__ src, float* __restrict__ dst,
                                 int R, int C, int dpitch)
{
    __shared__ float t[32][33];
    int c0 = blockIdx.x * 32, r0 = blockIdx.y * 32;
    int x = threadIdx.x, y = threadIdx.y;   // 32 x 8
    #pragma unroll
    for (int i = 0; i < 32; i += 8) {
        int r = r0 + y + i, c = c0 + x;
        t[y + i][x] = (r < R && c < C) ? src[(size_t)r * C + c] : 0.f;
    }
    __syncthreads();
    #pragma unroll
    for (int i = 0; i < 32; i += 8) {
        int c = c0 + y + i, r = r0 + x;
        if (c < C && r < R) dst[(size_t)c * dpitch + r] = t[x][y + i];
    }
}

__global__ void bias_kernel(
    const float* __restrict__ bz,  const float* __restrict__ bzl, const float* __restrict__ bzr,
    const float* __restrict__ br,  const float* __restrict__ brl, const float* __restrict__ brr,
    const float* __restrict__ bh,  const float* __restrict__ bhl, const float* __restrict__ bhr)
{
    int i = blockIdx.x * blockDim.x + threadIdx.x;
    if (i >= 1024) return;
    float bzs = bz[i] + bzl[i] + bzr[i];
    float brs = br[i] + brl[i] + brr[i];
    float bhs = bh[i] + bhl[i] + bhr[i];
    g_BZR[i] = bzs; g_BZR[1024 + i] = brs;
    g_BH[i]  = bhs;
    g_BL0[i] = bzs; g_BL0[1024 + i] = bhs;
}

// ================= mma.sync fp16x3 GEMM =================
// C(MxN) = A(MxK) @ Bt(NxK)^T + bias
// BM=BN=128, BK=32, 256 threads = 8 warps (4m x 2n), warp tile 32x64.
#define BM 128
#define BN 128
#define BK 32

// smem: padded fp16 tiles, row stride 40 halves (80 B) -> conflict-free ldmatrix
#define PAD_STRIDE 40
#define TILE_HBYTES (128 * PAD_STRIDE * 2)     // 10240 B per (hi|lo) half-tile
#define SA_H 0
#define SA_L (SA_H + TILE_HBYTES)
#define SB_H (SA_L + TILE_HBYTES)
#define SB_L (SB_H + TILE_HBYTES)
#define STAGE_BYTES (4 * TILE_HBYTES)          // 40960
#define SMEM_BYTES  (2 * STAGE_BYTES)          // 81920

__device__ __forceinline__ uint32_t smem_u32(const void* p) {
    uint32_t a;
    asm("{ .reg .u64 t; cvta.to.shared.u64 t, %1; cvt.u32.u64 %0, t; }" : "=r"(a) : "l"(p));
    return a;
}

#define LDSM4(r0, r1, r2, r3, addr)                                              \
    asm volatile("ldmatrix.sync.aligned.m8n8.x4.shared.b16 {%0,%1,%2,%3}, [%4];" \
        : "=r"(r0), "=r"(r1), "=r"(r2), "=r"(r3) : "r"(addr))

#define MMA16816(d, a, b0, b1)                                                   \
    asm volatile("mma.sync.aligned.m16n8k16.row.col.f32.f16.f16.f32 "            \
        "{%0,%1,%2,%3}, {%4,%5,%6,%7}, {%8,%9}, {%0,%1,%2,%3};"                  \
        : "+f"((d)[0]), "+f"((d)[1]), "+f"((d)[2]), "+f"((d)[3])                  \
        : "r"((a)[0]), "r"((a)[1]), "r"((a)[2]), "r"((a)[3]), "r"(b0), "r"(b1))

// fp32 -> (hi, lo) fp16 split, 4 lanes -> two uint2
__device__ __forceinline__ void split4_h(float4 v, uint2& hi, uint2& lo) {
    half hx = __float2half_rn(v.x), hy = __float2half_rn(v.y);
    half hz = __float2half_rn(v.z), hw = __float2half_rn(v.w);
    half lx = __float2half_rn(v.x - __half2float(hx));
    half ly = __float2half_rn(v.y - __half2float(hy));
    half lz = __float2half_rn(v.z - __half2float(hz));
    half lw = __float2half_rn(v.w - __half2float(hw));
    __half2 h01 = __halves2half2(hx, hy), h23 = __halves2half2(hz, hw);
    __half2 l01 = __halves2half2(lx, ly), l23 = __halves2half2(lz, lw);
    hi.x = *(uint32_t*)&h01; hi.y = *(uint32_t*)&h23;
    lo.x = *(uint32_t*)&l01; lo.y = *(uint32_t*)&l23;
}

template<bool GATHER>
__global__ void __launch_bounds__(256, 1)
gemm_mma_kernel(const float* __restrict__ A, const int* __restrict__ tok,
                const float* __restrict__ Bt, const float* __restrict__ bias,
                float* __restrict__ C, int M, int N, int K)
{
    extern __shared__ char smem[];
    const uint32_t sb = smem_u32(smem);
    const int tid  = threadIdx.x;
    const int lane = tid & 31;
    const int wid  = tid >> 5;
    const int warp_m = wid & 3;     // 0..3 -> 32 rows each
    const int warp_n = wid >> 2;    // 0..1 -> 64 cols each
    const int bm = blockIdx.y * BM, bn = blockIdx.x * BN;

    // ---- per-thread global load mapping (4 float4 of A + 4 of B per stage) ----
    const float* aptr[4]; const float* bptr[4]; uint32_t soff[4]; bool okA[4];
    #pragma unroll
    for (int i = 0; i < 4; i++) {
        int idx = tid + 256 * i;        // 0..1023
        int row = idx >> 3;             // 0..127
        int c4  = idx & 7;              // float4 index within 32-col row
        soff[i] = (uint32_t)(row * PAD_STRIDE * 2 + c4 * 8);   // bytes in half-tile
        int gr = bm + row;
        okA[i] = gr < M;
        int grc = okA[i] ? gr : 0;
        if (GATHER) aptr[i] = A + (size_t)__ldg(&tok[grc]) * K + c4 * 4;
        else        aptr[i] = A + (size_t)grc * K + c4 * 4;
        bptr[i] = Bt + (size_t)(bn + row) * K + c4 * 4;
    }

    // ---- per-lane ldmatrix address components ----
    const int a_row_l = lane & 15;                 // row within 16
    const int a_k_l   = (lane >> 4) * 8;           // k offset (elements)
    const int b_row_l = ((lane >> 4) << 3) + (lane & 7);
    const int b_k_l   = ((lane >> 3) & 1) * 8;

    const uint32_t a_lane_off = (uint32_t)((warp_m * 32 + a_row_l) * PAD_STRIDE * 2 + a_k_l * 2);
    const uint32_t b_lane_off = (uint32_t)((warp_n * 64 + b_row_l) * PAD_STRIDE * 2 + b_k_l * 2);

    float acc[2][8][4];
    #pragma unroll
    for (int mt = 0; mt < 2; mt++)
        #pragma unroll
        for (int t = 0; t < 8; t++)
            #pragma unroll
            for (int j = 0; j < 4; j++) acc[mt][t][j] = 0.f;

    const int NT = K / BK;
    float4 va[4], vb[4];

    // prologue: stage 0
    #pragma unroll
    for (int i = 0; i < 4; i++) {
        va[i] = okA[i] ? *(const float4*)aptr[i] : make_float4(0.f, 0.f, 0.f, 0.f);
        vb[i] = *(const float4*)bptr[i];
    }
    {
        char* base = smem;
        #pragma unroll
        for (int i = 0; i < 4; i++) {
            uint2 hi, lo;
            split4_h(va[i], hi, lo);
            *(uint2*)(base + SA_H + soff[i]) = hi;
            *(uint2*)(base + SA_L + soff[i]) = lo;
            split4_h(vb[i], hi, lo);
            *(uint2*)(base + SB_H + soff[i]) = hi;
            *(uint2*)(base + SB_L + soff[i]) = lo;
        }
    }
    __syncthreads();

    for (int kt = 0; kt < NT; kt++) {
        const int buf = kt & 1;
        // issue next-stage global loads early
        if (kt + 1 < NT) {
            #pragma unroll
            for (int i = 0; i < 4; i++) {
                va[i] = okA[i] ? *(const float4*)(aptr[i] + (kt + 1) * BK)
                               : make_float4(0.f, 0.f, 0.f, 0.f);
                vb[i] = *(const float4*)(bptr[i] + (kt + 1) * BK);
            }
        }

        // compute on current buffer: two k16 steps
        const uint32_t sbase = sb + buf * STAGE_BYTES;
        #pragma unroll
        for (int ks = 0; ks < 2; ks++) {
            const uint32_t koff = ks * 32;  // 16 elements * 2 bytes
            uint32_t ah[2][4], al[2][4], bh[4][4], bl[4][4];
            #pragma unroll
            for (int mt = 0; mt < 2; mt++) {
                uint32_t ad = sbase + SA_H + a_lane_off + mt * (16 * PAD_STRIDE * 2) + koff;
                LDSM4(ah[mt][0], ah[mt][1], ah[mt][2], ah[mt][3], ad);
                ad += (SA_L - SA_H);
                LDSM4(al[mt][0], al[mt][1], al[mt][2], al[mt][3], ad);
            }
            #pragma unroll
            for (int ng = 0; ng < 4; ng++) {
                uint32_t bd = sbase + SB_H + b_lane_off + ng * (16 * PAD_STRIDE * 2) + koff;
                LDSM4(bh[ng][0], bh[ng][1], bh[ng][2], bh[ng][3], bd);
                bd += (SB_L - SB_H);
                LDSM4(bl[ng][0], bl[ng][1], bl[ng][2], bl[ng][3], bd);
            }
            #pragma unroll
            for (int mt = 0; mt < 2; mt++)
                #pragma unroll
                for (int ng = 0; ng < 4; ng++)
                    #pragma unroll
                    for (int p = 0; p < 2; p++) {
                        float* c = acc[mt][ng * 2 + p];
                        MMA16816(c, ah[mt], bh[ng][2 * p], bh[ng][2 * p + 1]);
                        MMA16816(c, ah[mt], bl[ng][2 * p], bl[ng][2 * p + 1]);
                        MMA16816(c, al[mt], bh[ng][2 * p], bh[ng][2 * p + 1]);
                    }
        }

        // store next stage
        if (kt + 1 < NT) {
            char* base = smem + (buf ^ 1) * STAGE_BYTES;
            #pragma unroll
            for (int i = 0; i < 4; i++) {
                uint2 hi, lo;
                split4_h(va[i], hi, lo);
                *(uint2*)(base + SA_H + soff[i]) = hi;
                *(uint2*)(base + SA_L + soff[i]) = lo;
                split4_h(vb[i], hi, lo);
                *(uint2*)(base + SB_H + soff[i]) = hi;
                *(uint2*)(base + SB_L + soff[i]) = lo;
            }
            __syncthreads();
        }
    }

    // ---- epilogue: fragment -> gmem with bias ----
    const int r0 = bm + warp_m * 32 + (lane >> 2);
    const int c0 = bn + warp_n * 64 + (lane & 3) * 2;
    #pragma unroll
    for (int mt = 0; mt < 2; mt++) {
        const int row = r0 + mt * 16;
        #pragma unroll
        for (int t = 0; t < 8; t++) {
            const int col = c0 + t * 8;
            const float b0 = bias[col], b1 = bias[col + 1];
            if (row < M) {
                float2 v = make_float2(acc[mt][t][0] + b0, acc[mt][t][1] + b1);
                *(float2*)(C + (size_t)row * N + col) = v;
            }
            if (row + 8 < M) {
                float2 v = make_float2(acc[mt][t][2] + b0, acc[mt][t][3] + b1);
                *(float2*)(C + (size_t)(row + 8) * N + col) = v;
            }
        }
    }
}

// ================= elementwise epilogues (float4) =================
__device__ __forceinline__ float sigmf(float x) { return 1.f / (1.f + expf(-x)); }

// level 0: pre = [zpre | hpre] (M x 2048) -> h0 = (1-z)*tanh(hpre)
__global__ void e0_kernel(const float* __restrict__ pre, float* __restrict__ h0, int total4)
{
    int q = blockIdx.x * blockDim.x + threadIdx.x;
    if (q >= total4) return;
    int idx = q * 4;
    int m = idx >> 10, j = idx & 1023;
    size_t o = (size_t)m * 2048 + j;
    float4 zp = *(const float4*)(pre + o);
    float4 hp = *(const float4*)(pre + o + 1024);
    float4 r;
    r.x = (1.f - sigmf(zp.x)) * tanhf(hp.x);
    r.y = (1.f - sigmf(zp.y)) * tanhf(hp.y);
    r.z = (1.f - sigmf(zp.z)) * tanhf(hp.z);
    r.w = (1.f - sigmf(zp.w)) * tanhf(hp.w);
    *(float4*)(h0 + idx) = r;
}

// after GEMM1: pre = [zpre | rpre]; hprev viewed (M,2048) = [hl|hr]
__global__ void e1_kernel(const float* __restrict__ pre, const float* __restrict__ hprev,
                          float* __restrict__ zb, float* __restrict__ rh, int total4)
{
    int q = blockIdx.x * blockDim.x + threadIdx.x;
    if (q >= total4) return;
    int idx = q * 4;
    int m = idx >> 10, j = idx & 1023;
    size_t o = (size_t)m * 2048 + j;
    float4 zp = *(const float4*)(pre + o);
    float4 rp = *(const float4*)(pre + o + 1024);
    float4 hl = *(const float4*)(hprev + o);
    float4 hr = *(const float4*)(hprev + o + 1024);
    float4 z, q0, q1;
    z.x = sigmf(zp.x); z.y = sigmf(zp.y); z.z = sigmf(zp.z); z.w = sigmf(zp.w);
    float rx = sigmf(rp.x), ry = sigmf(rp.y), rz = sigmf(rp.z), rw = sigmf(rp.w);
    q0.x = rx * hl.x; q0.y = ry * hl.y; q0.z = rz * hl.z; q0.w = rw * hl.w;
    q1.x = rx * hr.x; q1.y = ry * hr.y; q1.z = rz * hr.z; q1.w = rw * hr.w;
    *(float4*)(zb + idx) = z;
    *(float4*)(rh + o) = q0;
    *(float4*)(rh + o + 1024) = q1;
}

// after GEMM2: h = z*(hl+hr) + (1-z)*tanh(pre2)
__global__ void e2_kernel(const float* __restrict__ pre2, const float* __restrict__ zb,
                          const float* __restrict__ hprev, float* __restrict__ hout, int total4)
{
    int q = blockIdx.x * blockDim.x + threadIdx.x;
    if (q >= total4) return;
    int idx = q * 4;
    int m = idx >> 10, j = idx & 1023;
    size_t o = (size_t)m * 2048 + j;
    float4 z  = *(const float4*)(zb + idx);
    float4 hl = *(const float4*)(hprev + o);
    float4 hr = *(const float4*)(hprev + o + 1024);
    float4 p  = *(const float4*)(pre2 + idx);
    float4 r;
    r.x = z.x * (hl.x + hr.x) + (1.f - z.x) * tanhf(p.x);
    r.y = z.y * (hl.y + hr.y) + (1.f - z.y) * tanhf(p.y);
    r.z = z.z * (hl.z + hr.z) + (1.f - z.z) * tanhf(p.z);
    r.w = z.w * (hl.w + hr.w) + (1.f - z.w) * tanhf(p.w);
    *(float4*)(hout + idx) = r;
}

// ================= launch =================
extern "C" void kernel_launch(void* const* d_in, const int* in_sizes, int n_in,
                              void* d_out, int out_size)
{
    const int*   tokens = (const int*)  d_in[0];
    const float* emb    = (const float*)d_in[1];
    const float* W_z  = (const float*)d_in[2];
    const float* b_z  = (const float*)d_in[3];
    const float* U_zl = (const float*)d_in[4];
    const float* b_zl = (const float*)d_in[5];
    const float* U_zr = (const float*)d_in[6];
    const float* b_zr = (const float*)d_in[7];
    const float* W_r  = (const float*)d_in[8];
    const float* b_r  = (const float*)d_in[9];
    const float* U_rl = (const float*)d_in[10];
    const float* b_rl = (const float*)d_in[11];
    const float* U_rr = (const float*)d_in[12];
    const float* b_rr = (const float*)d_in[13];
    const float* W_h  = (const float*)d_in[14];
    const float* b_h  = (const float*)d_in[15];
    const float* U_hl = (const float*)d_in[16];
    const float* b_hl = (const float*)d_in[17];
    const float* U_hr = (const float*)d_in[18];
    const float* b_hr = (const float*)d_in[19];
    (void)W_r; // level-0 r is multiplied by hl=hr=0

    float *HB0, *HB1, *PRE, *RH, *ZB, *W0t, *UZRt, *UHt, *BL0, *BZR, *BH;
    cudaGetSymbolAddress((void**)&HB0,  g_HB0);
    cudaGetSymbolAddress((void**)&HB1,  g_HB1);
    cudaGetSymbolAddress((void**)&PRE,  g_PRE);
    cudaGetSymbolAddress((void**)&RH,   g_RH);
    cudaGetSymbolAddress((void**)&ZB,   g_Z);
    cudaGetSymbolAddress((void**)&W0t,  g_W0t);
    cudaGetSymbolAddress((void**)&UZRt, g_UZRt);
    cudaGetSymbolAddress((void**)&UHt,  g_UHt);
    cudaGetSymbolAddress((void**)&BL0,  g_BL0);
    cudaGetSymbolAddress((void**)&BZR,  g_BZR);
    cudaGetSymbolAddress((void**)&BH,   g_BH);

    cudaFuncSetAttribute(gemm_mma_kernel<true>,
                         cudaFuncAttributeMaxDynamicSharedMemorySize, SMEM_BYTES);
    cudaFuncSetAttribute(gemm_mma_kernel<false>,
                         cudaFuncAttributeMaxDynamicSharedMemorySize, SMEM_BYTES);

    // ---- pack: transpose weights into [N][K] K-major ----
    {
        dim3 blk(32, 8);
        dim3 g32(1024 / 32, 1024 / 32);
        transpose_kernel<<<g32, blk>>>(U_zl, UZRt,                              1024, 1024, 2048);
        transpose_kernel<<<g32, blk>>>(U_rl, UZRt + (size_t)1024 * 2048,        1024, 1024, 2048);
        transpose_kernel<<<g32, blk>>>(U_zr, UZRt + 1024,                       1024, 1024, 2048);
        transpose_kernel<<<g32, blk>>>(U_rr, UZRt + (size_t)1024 * 2048 + 1024, 1024, 1024, 2048);
        transpose_kernel<<<g32, blk>>>(U_hl, UHt,        1024, 1024, 2048);
        transpose_kernel<<<g32, blk>>>(U_hr, UHt + 1024, 1024, 1024, 2048);
        dim3 gW(1024 / 32, 512 / 32);
        transpose_kernel<<<gW, blk>>>(W_z, W0t,                       512, 1024, 512);
        transpose_kernel<<<gW, blk>>>(W_h, W0t + (size_t)1024 * 512,  512, 1024, 512);
        bias_kernel<<<4, 256>>>(b_z, b_zl, b_zr, b_r, b_rl, b_rr, b_h, b_hl, b_hr);
    }

    // ---- level 0: pre = emb[tokens] @ [W_z|W_h]^T_packed + [bz|bh] ----
    {
        dim3 grid(2 * HDIM / BN, M0 / BM);
        gemm_mma_kernel<true><<<grid, 256, SMEM_BYTES>>>(emb, tokens, W0t, BL0, PRE,
                                                         M0, 2 * HDIM, EDIM);
        int total4 = M0 * HDIM / 4;
        e0_kernel<<<(total4 + 255) / 256, 256>>>(PRE, HB0, total4);
    }

    // ---- tree levels: n = 512 -> 1 ----
    float* hprev = HB0;
    int n = SEQ, lvl = 0;
    while (n > 1) {
        int Mn = BATCH * (n / 2);
        float* hout = (n / 2 == 1) ? (float*)d_out : ((lvl & 1) ? HB0 : HB1);
        int gy = (Mn + BM - 1) / BM;

        // GEMM1: [hl|hr](Mn x 2048) @ UZR + [bz|br]
        {
            dim3 grid(2 * HDIM / BN, gy);
            gemm_mma_kernel<false><<<grid, 256, SMEM_BYTES>>>(hprev, nullptr, UZRt, BZR, PRE,
                                                              Mn, 2 * HDIM, 2 * HDIM);
        }
        {
            int total4 = Mn * HDIM / 4;
            e1_kernel<<<(total4 + 255) / 256, 256>>>(PRE, hprev, ZB, RH, total4);
        }
        // GEMM2: [r*hl|r*hr](Mn x 2048) @ UH + bh
        {
            dim3 grid(HDIM / BN, gy);
            gemm_mma_kernel<false><<<grid, 256, SMEM_BYTES>>>(RH, nullptr, UHt, BH, PRE,
                                                              Mn, HDIM, 2 * HDIM);
        }
        {
            int total4 = Mn * HDIM / 4;
            e2_kernel<<<(total4 + 255) / 256, 256>>>(PRE, ZB, hprev, hout, total4);
        }

        hprev = hout;
        n /= 2;
        lvl++;
    }
    (void)in_sizes; (void)n_in; (void)out_size;
}